// round 2
// baseline (speedup 1.0000x reference)
#include <cuda_runtime.h>
#include <cstdint>

typedef unsigned long long ull;

#define DIM    64
#define CODES  512
#define NTOK   262144          // 64*64*64 tokens
#define TPB    256
#define TM     2               // tokens per thread
#define TOKPB  (TPB * TM)      // 512 tokens per block
#define NBLK   (NTOK / TOKPB)  // 512
#define SROW   68              // floats per code row in smem (64 + pad), 272B
#define SROW_V2 17             // ulonglong2 per code row

// Output layout (float32, concatenated tuple):
// quantize_st[64^4], quant_loss[1], indices[64^3], commitment_loss[1],
// embedding_new[64*512], N_new[512], M_new[64*512]
#define OFF_Q    0L
#define OFF_QL   16777216L
#define OFF_IDX  16777217L
#define OFF_CL   17039361L
#define OFF_EMB  17039362L
#define OFF_N    17072130L
#define OFF_M    17072642L

#define SMEM_BYTES ((CODES*SROW + CODES + TOKPB) * 4)

__device__ float g_eNorm[CODES];
__device__ float g_ni[CODES];
__device__ float g_eofxT[CODES * DIM];   // transposed: [code][dim]
__device__ float g_loss;

// ---- packed f32x2 helpers (ptxas won't auto-fuse; PTX only) ----
__device__ __forceinline__ ull fma2(ull a, ull b, ull c) {
    ull d; asm("fma.rn.f32x2 %0, %1, %2, %3;" : "=l"(d) : "l"(a), "l"(b), "l"(c)); return d;
}
__device__ __forceinline__ ull add2(ull a, ull b) {
    ull d; asm("add.rn.f32x2 %0, %1, %2;" : "=l"(d) : "l"(a), "l"(b)); return d;
}
__device__ __forceinline__ float sum2(ull a) {
    float lo, hi; asm("mov.b64 {%0,%1}, %2;" : "=f"(lo), "=f"(hi) : "l"(a)); return lo + hi;
}
__device__ __forceinline__ void unpack2(ull a, float& lo, float& hi) {
    asm("mov.b64 {%0,%1}, %2;" : "=f"(lo), "=f"(hi) : "l"(a));
}
__device__ __forceinline__ void red_v2(float* p, float a, float b) {
    asm volatile("red.global.add.v2.f32 [%0], {%1, %2};"
                 :: "l"(p), "f"(a), "f"(b) : "memory");
}

// ---- kernel 1: zero scratch + codebook column norms ----
__global__ void vq_prep(const float* __restrict__ emb) {
    int tid = blockIdx.x * blockDim.x + threadIdx.x;
    if (tid < DIM * CODES) g_eofxT[tid] = 0.f;
    if (tid < CODES) {
        g_ni[tid] = 0.f;
        float s = 0.f;
        #pragma unroll
        for (int d = 0; d < DIM; d++) {
            float v = emb[d * CODES + tid];
            s = fmaf(v, v, s);
        }
        g_eNorm[tid] = s;
    }
    if (tid == 0) g_loss = 0.f;
}

// ---- kernel 2: fused assign / quantize / loss / segment sums ----
extern __shared__ float smem[];

__global__ void __launch_bounds__(TPB, 1)
vq_main(const float* __restrict__ x, const float* __restrict__ emb,
        float* __restrict__ out) {
    float* sE    = smem;                    // [CODES][SROW]
    float* sNorm = sE + CODES * SROW;       // [CODES]
    int*   sIdx  = (int*)(sNorm + CODES);   // [TOKPB]

    const int tid = threadIdx.x;

    // load embedding transposed: sE[c][d] = emb[d*CODES + c]
    #pragma unroll
    for (int k = 0; k < (DIM * CODES) / TPB; k++) {
        int idx = k * TPB + tid;
        int d = idx >> 9, c = idx & (CODES - 1);
        sE[c * SROW + d] = emb[idx];
    }
    #pragma unroll
    for (int k = 0; k < CODES / TPB; k++) {
        int c = k * TPB + tid;
        sNorm[c] = g_eNorm[c];
    }

    const int tokenA = blockIdx.x * TOKPB + tid;
    const int tokenB = tokenA + TPB;
    ull xA[32], xB[32];  // 64 floats each, packed as f32x2
    {
        const ulonglong2* ga = (const ulonglong2*)(x + (size_t)tokenA * DIM);
        const ulonglong2* gb = (const ulonglong2*)(x + (size_t)tokenB * DIM);
        #pragma unroll
        for (int j = 0; j < 16; j++) {
            ulonglong2 va = ga[j], vb = gb[j];
            xA[2 * j] = va.x; xA[2 * j + 1] = va.y;
            xB[2 * j] = vb.x; xB[2 * j + 1] = vb.y;
        }
    }
    __syncthreads();

    // argmin over codes of  ||e||^2 - 2 x.e   (||x||^2 constant per token)
    float bestA = 3.402823466e38f, bestB = 3.402823466e38f;
    int bcA = 0, bcB = 0;
    const ulonglong2* ebase = (const ulonglong2*)sE;

    #pragma unroll 1
    for (int c = 0; c < CODES; c += 4) {
        const ulonglong2* e0 = ebase + (size_t)c * SROW_V2;
        const ulonglong2* e1 = e0 + SROW_V2;
        const ulonglong2* e2 = e1 + SROW_V2;
        const ulonglong2* e3 = e2 + SROW_V2;
        ull a0A = 0, b0A = 0, a1A = 0, b1A = 0, a2A = 0, b2A = 0, a3A = 0, b3A = 0;
        ull a0B = 0, b0B = 0, a1B = 0, b1B = 0, a2B = 0, b2B = 0, a3B = 0, b3B = 0;
        #pragma unroll
        for (int j = 0; j < 16; j++) {
            ulonglong2 v0 = e0[j], v1 = e1[j], v2 = e2[j], v3 = e3[j];
            ull xl = xA[2 * j], xh = xA[2 * j + 1];
            a0A = fma2(xl, v0.x, a0A); b0A = fma2(xh, v0.y, b0A);
            a1A = fma2(xl, v1.x, a1A); b1A = fma2(xh, v1.y, b1A);
            a2A = fma2(xl, v2.x, a2A); b2A = fma2(xh, v2.y, b2A);
            a3A = fma2(xl, v3.x, a3A); b3A = fma2(xh, v3.y, b3A);
            ull yl = xB[2 * j], yh = xB[2 * j + 1];
            a0B = fma2(yl, v0.x, a0B); b0B = fma2(yh, v0.y, b0B);
            a1B = fma2(yl, v1.x, a1B); b1B = fma2(yh, v1.y, b1B);
            a2B = fma2(yl, v2.x, a2B); b2B = fma2(yh, v2.y, b2B);
            a3B = fma2(yl, v3.x, a3B); b3B = fma2(yh, v3.y, b3B);
        }
        float n0 = sNorm[c], n1 = sNorm[c + 1], n2 = sNorm[c + 2], n3 = sNorm[c + 3];
        float d0 = fmaf(-2.f, sum2(add2(a0A, b0A)), n0);
        float d1 = fmaf(-2.f, sum2(add2(a1A, b1A)), n1);
        float d2 = fmaf(-2.f, sum2(add2(a2A, b2A)), n2);
        float d3 = fmaf(-2.f, sum2(add2(a3A, b3A)), n3);
        if (d0 < bestA) { bestA = d0; bcA = c; }
        if (d1 < bestA) { bestA = d1; bcA = c + 1; }
        if (d2 < bestA) { bestA = d2; bcA = c + 2; }
        if (d3 < bestA) { bestA = d3; bcA = c + 3; }
        d0 = fmaf(-2.f, sum2(add2(a0B, b0B)), n0);
        d1 = fmaf(-2.f, sum2(add2(a1B, b1B)), n1);
        d2 = fmaf(-2.f, sum2(add2(a2B, b2B)), n2);
        d3 = fmaf(-2.f, sum2(add2(a3B, b3B)), n3);
        if (d0 < bestB) { bestB = d0; bcB = c; }
        if (d1 < bestB) { bestB = d1; bcB = c + 1; }
        if (d2 < bestB) { bestB = d2; bcB = c + 2; }
        if (d3 < bestB) { bestB = d3; bcB = c + 3; }
    }

    sIdx[tid] = bcA;
    sIdx[TPB + tid] = bcB;
    out[OFF_IDX + tokenA] = (float)bcA;
    out[OFF_IDX + tokenB] = (float)bcB;
    atomicAdd(&g_ni[bcA], 1.0f);
    atomicAdd(&g_ni[bcB], 1.0f);

    // loss partials + eofx segment-sum scatter (transposed layout, red.v2)
    float lsum = 0.f;
    {
        const float* eb = sE + bcA * SROW;
        float* gb = g_eofxT + bcA * DIM;
        #pragma unroll
        for (int j = 0; j < 32; j++) {
            float x0, x1; unpack2(xA[j], x0, x1);
            float t0 = x0 - eb[2 * j], t1 = x1 - eb[2 * j + 1];
            lsum = fmaf(t0, t0, lsum);
            lsum = fmaf(t1, t1, lsum);
            red_v2(gb + 2 * j, x0, x1);
        }
    }
    {
        const float* eb = sE + bcB * SROW;
        float* gb = g_eofxT + bcB * DIM;
        #pragma unroll
        for (int j = 0; j < 32; j++) {
            float x0, x1; unpack2(xB[j], x0, x1);
            float t0 = x0 - eb[2 * j], t1 = x1 - eb[2 * j + 1];
            lsum = fmaf(t0, t0, lsum);
            lsum = fmaf(t1, t1, lsum);
            red_v2(gb + 2 * j, x0, x1);
        }
    }
    #pragma unroll
    for (int o = 16; o > 0; o >>= 1)
        lsum += __shfl_xor_sync(0xffffffffu, lsum, o);
    if ((tid & 31) == 0) atomicAdd(&g_loss, lsum);

    // coalesced vectorized quantize_st write (q == quantize numerically)
    __syncthreads();
    float4* out4 = (float4*)(out + OFF_Q) + (size_t)blockIdx.x * (TOKPB * DIM / 4);
    #pragma unroll 1
    for (int it = 0; it < (TOKPB * DIM / 4) / TPB; it++) {   // 32 iters
        int idx4 = it * TPB + tid;
        int t = idx4 >> 4, dq = idx4 & 15;
        out4[idx4] = ((const float4*)(sE + sIdx[t] * SROW))[dq];
    }
}

// ---- kernel 3: EMA update + smoothing + losses ----
__global__ void vq_finalize(const float* __restrict__ Nin,
                            const float* __restrict__ Min,
                            float* __restrict__ out) {
    __shared__ float red[CODES];
    const int c = threadIdx.x;
    const float DEC = 0.99f, OMD = 1.0f - 0.99f;

    float Nn = fmaf(Nin[c], DEC, OMD * g_ni[c]);
    out[OFF_N + c] = Nn;
    red[c] = Nn;
    __syncthreads();
    for (int s = CODES / 2; s > 0; s >>= 1) {
        if (c < s) red[c] += red[c + s];
        __syncthreads();
    }
    float n = red[0];
    float Ns = (Nn + 1e-5f) / (n + CODES * 1e-5f) * n;

    #pragma unroll
    for (int d = 0; d < DIM; d++) {
        int i = d * CODES + c;
        float Mn = fmaf(Min[i], DEC, OMD * g_eofxT[c * DIM + d]);
        out[OFF_M + i] = Mn;
        out[OFF_EMB + i] = Mn / Ns;
    }
    if (c == 0) {
        float l = g_loss * (1.0f / 16777216.0f);
        out[OFF_QL] = l;   // quant_loss
        out[OFF_CL] = l;   // commitment_loss (numerically identical)
    }
}

extern "C" void kernel_launch(void* const* d_in, const int* in_sizes, int n_in,
                              void* d_out, int out_size) {
    const float* x   = (const float*)d_in[0];
    const float* emb = (const float*)d_in[1];
    const float* N   = (const float*)d_in[2];
    const float* M   = (const float*)d_in[3];
    float* out = (float*)d_out;

    cudaFuncSetAttribute(vq_main, cudaFuncAttributeMaxDynamicSharedMemorySize,
                         SMEM_BYTES);

    vq_prep<<<(DIM * CODES + 255) / 256, 256>>>(emb);
    vq_main<<<NBLK, TPB, SMEM_BYTES>>>(x, emb, out);
    vq_finalize<<<1, CODES>>>(N, M, out);
}